// round 10
// baseline (speedup 1.0000x reference)
#include <cuda_runtime.h>
#include <cuda_fp16.h>
#include <cstdint>
#include <math.h>

// LSTM cell: fp16 mma.sync GEMM + register-direct fused gate epilogue.
// Round 10: exact round-7 GEMM shape (BM=128, BK=64, 78 regs, no frag
// double-buffer) but __launch_bounds__(256,3): 3 CTAs/SM (221KB smem, 24 warps).

#define BATCH 4096
#define UNITS 1024
#define KDIM  2048

#define BM 128
#define BNU 32              // units per CTA (x4 gates = 128 gemm cols)
#define BK 64
#define NSTAGE (KDIM / BK)  // 32
#define NBUF 2

#define ROW_B   144                     // 128B data + 16B pad (conflict-free)
#define TILE_B  (128 * ROW_B)           // 18432
#define OFF_AH  0
#define OFF_BH  TILE_B
#define STAGE_B (2 * TILE_B)            // 36864
#define SMEM_TOTAL (NBUF * STAGE_B)     // 73728

// ---------------- device scratch ----------------
__device__ __half g_Ah[(size_t)BATCH * KDIM];
__device__ __half g_Bh[(size_t)4 * UNITS * KDIM];   // row = gate*1024 + n, k contiguous

// ---------------- helpers ----------------
__device__ __forceinline__ uint32_t smem_u32(const void* p) {
    uint32_t a;
    asm("{ .reg .u64 t; cvta.to.shared.u64 t, %1; cvt.u32.u64 %0, t; }" : "=r"(a) : "l"(p));
    return a;
}
__device__ __forceinline__ void cp16(uint32_t dst, const void* src) {
    asm volatile("cp.async.cg.shared.global [%0], [%1], 16;" :: "r"(dst), "l"(src));
}
#define CP_COMMIT() asm volatile("cp.async.commit_group;" ::: "memory")
#define CP_WAIT(n)  asm volatile("cp.async.wait_group %0;" :: "n"(n) : "memory")

#define LDSM4(r0, r1, r2, r3, addr) \
    asm volatile("ldmatrix.sync.aligned.m8n8.x4.shared.b16 {%0,%1,%2,%3}, [%4];" \
        : "=r"(r0), "=r"(r1), "=r"(r2), "=r"(r3) : "r"(addr))

__device__ __forceinline__ void mma_f16(float* c, const uint32_t* a, const uint32_t* b) {
    asm volatile(
        "mma.sync.aligned.m16n8k16.row.col.f32.f16.f16.f32 "
        "{%0,%1,%2,%3}, {%4,%5,%6,%7}, {%8,%9}, {%0,%1,%2,%3};"
        : "+f"(c[0]), "+f"(c[1]), "+f"(c[2]), "+f"(c[3])
        : "r"(a[0]), "r"(a[1]), "r"(a[2]), "r"(a[3]), "r"(b[0]), "r"(b[1]));
}

__device__ __forceinline__ float sig_(float x) {
    x = fminf(fmaxf(x, -30.f), 30.f);
    return __fdividef(1.f, 1.f + __expf(-x));
}
__device__ __forceinline__ float tanh_(float x) {
    x = fminf(fmaxf(x, -15.f), 15.f);
    float e = __expf(2.f * x);
    return __fdividef(e - 1.f, e + 1.f);
}

// ---------------- merged precompute: A convert + W^T convert ----------------
__global__ __launch_bounds__(256) void prep_kernel(
    const float* __restrict__ hid, const float* __restrict__ inp,
    const float* __restrict__ Wf, const float* __restrict__ Wi,
    const float* __restrict__ Wc, const float* __restrict__ Wo)
{
    __shared__ float tile[32][33];
    const int bid = blockIdx.x;
    if (bid < 8192) {
        int i4 = bid * 256 + threadIdx.x;   // float4 index over [4096][512]
        int row = i4 >> 9;
        int c4  = i4 & 511;
        const float4 v = (c4 < 256)
            ? *(const float4*)&hid[(size_t)row * 1024 + c4 * 4]
            : *(const float4*)&inp[(size_t)row * 1024 + (c4 - 256) * 4];
        __half h[4];
        h[0] = __float2half_rn(v.x);
        h[1] = __float2half_rn(v.y);
        h[2] = __float2half_rn(v.z);
        h[3] = __float2half_rn(v.w);
        *(uint2*)&g_Ah[(size_t)row * KDIM + c4 * 4] = *(uint2*)h;
    } else {
        const int t  = bid - 8192;          // 8192 blocks: gate(4) x k(64) x n(32)
        const int g  = t >> 11;
        const int k0 = ((t >> 5) & 63) * 32;
        const int n0 = (t & 31) * 32;
        const float* W = (g == 0) ? Wf : (g == 1) ? Wi : (g == 2) ? Wc : Wo;
        const int tx = threadIdx.x & 31;
        const int ty = threadIdx.x >> 5;   // 0..7
        #pragma unroll
        for (int j = 0; j < 4; j++)
            tile[ty + 8 * j][tx] = W[(size_t)(k0 + ty + 8 * j) * UNITS + n0 + tx];
        __syncthreads();
        const int n_l = threadIdx.x >> 3;        // 0..31
        const int kq  = (threadIdx.x & 7) * 4;   // 0..28
        __half h[4];
        #pragma unroll
        for (int j = 0; j < 4; j++)
            h[j] = __float2half_rn(tile[kq + j][n_l]);
        size_t o = ((size_t)g * UNITS + n0 + n_l) * KDIM + k0 + kq;
        *(uint2*)&g_Bh[o] = *(uint2*)h;
    }
}

// ---------------- fused GEMM + register epilogue ----------------
__global__ __launch_bounds__(256, 3) void gemm_kernel(
    const float* __restrict__ cell,
    const float* __restrict__ bfp, const float* __restrict__ bip,
    const float* __restrict__ bcp, const float* __restrict__ bop,
    float* __restrict__ out_h, float* __restrict__ out_c)
{
    extern __shared__ char smem[];
    const uint32_t sb = smem_u32(smem);
    const int tid  = threadIdx.x;
    const int wid  = tid >> 5;
    const int lane = tid & 31;
    const int warp_m = wid & 1;    // 64 rows
    const int warp_n = wid >> 1;   // 0..3 -> 8 units each, all 4 gates
    const int m0 = blockIdx.y * BM;
    const int n0 = blockIdx.x * BNU;

    auto issue_stage = [&](int s) {
        const int k0 = s * BK;
        const uint32_t base = sb + (s & 1) * STAGE_B;
        #pragma unroll
        for (int i = 0; i < 4; i++) {
            const int idx = tid + i * 256;
            const int row = idx >> 3;
            const int c   = idx & 7;
            cp16(base + OFF_AH + row * ROW_B + c * 16,
                 &g_Ah[(size_t)(m0 + row) * KDIM + k0 + c * 8]);
            const size_t gr = (size_t)(row >> 5) * UNITS + n0 + (row & 31);
            cp16(base + OFF_BH + row * ROW_B + c * 16,
                 &g_Bh[gr * KDIM + k0 + c * 8]);
        }
        CP_COMMIT();
    };

    // ldmatrix lane addressing (byte offsets within tiles)
    const uint32_t a_off = (uint32_t)((warp_m * 64 + (lane & 15)) * ROW_B + (lane >> 4) * 16);
    // B: [gate 2p | gate 2p+1] x [k0-7 | k8-15] per LDSM4
    const uint32_t b_off = (uint32_t)((((lane >> 4) & 1) * 32 + warp_n * 8 + (lane & 7)) * ROW_B
                                      + ((lane >> 3) & 1) * 16);

    float acc[4][4][4];   // [mt rows][gate][q]
    #pragma unroll
    for (int i = 0; i < 4; i++)
        #pragma unroll
        for (int j = 0; j < 4; j++)
            #pragma unroll
            for (int q = 0; q < 4; q++) acc[i][j][q] = 0.f;

    issue_stage(0);

    #pragma unroll 1
    for (int s = 0; s < NSTAGE; s++) {
        if (s + 1 < NSTAGE) { issue_stage(s + 1); CP_WAIT(1); }
        else                { CP_WAIT(0); }
        __syncthreads();

        const uint32_t base = sb + (s & 1) * STAGE_B;
        #pragma unroll
        for (int ksub = 0; ksub < 4; ksub++) {
            const uint32_t kb = ksub * 32;
            uint32_t aH[4][4], bH[4][2];
            #pragma unroll
            for (int mt = 0; mt < 4; mt++) {
                const uint32_t ra = base + a_off + mt * 16 * ROW_B + kb;
                LDSM4(aH[mt][0], aH[mt][1], aH[mt][2], aH[mt][3], ra + OFF_AH);
            }
            #pragma unroll
            for (int p = 0; p < 2; p++) {
                const uint32_t rb = base + b_off + p * 64 * ROW_B + kb;
                LDSM4(bH[2*p][0], bH[2*p][1], bH[2*p+1][0], bH[2*p+1][1], rb + OFF_BH);
            }
            #pragma unroll
            for (int mt = 0; mt < 4; mt++)
                #pragma unroll
                for (int g = 0; g < 4; g++)
                    mma_f16(acc[mt][g], aH[mt], bH[g]);
        }
        __syncthreads();
    }

    // ---- register-direct epilogue
    const int fr = lane >> 2;
    const int fc = (lane & 3) * 2;
    const int ucol = n0 + warp_n * 8 + fc;
    const float2 Bf = *(const float2*)&bfp[ucol];
    const float2 Bi = *(const float2*)&bip[ucol];
    const float2 Bc = *(const float2*)&bcp[ucol];
    const float2 Bo = *(const float2*)&bop[ucol];

    #pragma unroll
    for (int mt = 0; mt < 4; mt++) {
        #pragma unroll
        for (int q = 0; q < 2; q++) {
            const int row = m0 + warp_m * 64 + mt * 16 + fr + q * 8;
            const size_t go = (size_t)row * UNITS + ucol;
            const float2 cp = *(const float2*)&cell[go];
            const float pf0 = acc[mt][0][2*q],   pf1 = acc[mt][0][2*q+1];
            const float pi0 = acc[mt][1][2*q],   pi1 = acc[mt][1][2*q+1];
            const float pc0 = acc[mt][2][2*q],   pc1 = acc[mt][2][2*q+1];
            const float po0 = acc[mt][3][2*q],   po1 = acc[mt][3][2*q+1];

            float2 nh, nc;
            {
                const float f  = sig_(pf0 + Bf.x), ig = sig_(pi0 + Bi.x);
                const float cc = tanh_(pc0 + Bc.x), o = sig_(po0 + Bo.x);
                nc.x = f * cp.x + ig * cc; nh.x = o * tanh_(nc.x);
            }
            {
                const float f  = sig_(pf1 + Bf.y), ig = sig_(pi1 + Bi.y);
                const float cc = tanh_(pc1 + Bc.y), o = sig_(po1 + Bo.y);
                nc.y = f * cp.y + ig * cc; nh.y = o * tanh_(nc.y);
            }
            *(float2*)&out_h[go] = nh;
            *(float2*)&out_c[go] = nc;
        }
    }
}

// ---------------- host launch ----------------
extern "C" void kernel_launch(void* const* d_in, const int* in_sizes, int n_in,
                              void* d_out, int out_size) {
    const float* inp  = (const float*)d_in[0];
    const float* hid  = (const float*)d_in[1];
    const float* cell = (const float*)d_in[2];
    const float* Wf   = (const float*)d_in[3];
    const float* bf   = (const float*)d_in[4];
    const float* Wi   = (const float*)d_in[5];
    const float* bi   = (const float*)d_in[6];
    const float* Wc   = (const float*)d_in[7];
    const float* bc   = (const float*)d_in[8];
    const float* Wo   = (const float*)d_in[9];
    const float* bo   = (const float*)d_in[10];

    float* out_h = (float*)d_out;
    float* out_c = out_h + (size_t)BATCH * UNITS;

    cudaFuncSetAttribute(gemm_kernel,
                         cudaFuncAttributeMaxDynamicSharedMemorySize, SMEM_TOTAL);

    prep_kernel<<<16384, 256>>>(hid, inp, Wf, Wi, Wc, Wo);
    gemm_kernel<<<dim3(UNITS / BNU, BATCH / BM), 256, SMEM_TOTAL>>>(
        cell, bf, bi, bc, bo, out_h, out_c);
}

// round 11
// speedup vs baseline: 1.9466x; 1.9466x over previous
#include <cuda_runtime.h>
#include <cuda_fp16.h>
#include <cstdint>
#include <math.h>

// LSTM cell: fp16 mma.sync GEMM + register-direct fused gate epilogue.
// Round 11: round-7 shape (BM=128, BK=64, 2 CTAs/SM, 78 regs) with a
// single-barrier pipeline stage (CP_WAIT(0); bar; issue(s+1); compute(s))
// and the merged prep kernel.

#define BATCH 4096
#define UNITS 1024
#define KDIM  2048

#define BM 128
#define BNU 32              // units per CTA (x4 gates = 128 gemm cols)
#define BK 64
#define NSTAGE (KDIM / BK)  // 32
#define NBUF 2

#define ROW_B   144                     // 128B data + 16B pad (conflict-free)
#define TILE_B  (128 * ROW_B)           // 18432
#define OFF_AH  0
#define OFF_BH  TILE_B
#define STAGE_B (2 * TILE_B)            // 36864
#define SMEM_TOTAL (NBUF * STAGE_B)     // 73728

// ---------------- device scratch ----------------
__device__ __half g_Ah[(size_t)BATCH * KDIM];
__device__ __half g_Bh[(size_t)4 * UNITS * KDIM];   // row = gate*1024 + n, k contiguous

// ---------------- helpers ----------------
__device__ __forceinline__ uint32_t smem_u32(const void* p) {
    uint32_t a;
    asm("{ .reg .u64 t; cvta.to.shared.u64 t, %1; cvt.u32.u64 %0, t; }" : "=r"(a) : "l"(p));
    return a;
}
__device__ __forceinline__ void cp16(uint32_t dst, const void* src) {
    asm volatile("cp.async.cg.shared.global [%0], [%1], 16;" :: "r"(dst), "l"(src));
}
#define CP_COMMIT() asm volatile("cp.async.commit_group;" ::: "memory")
#define CP_WAIT(n)  asm volatile("cp.async.wait_group %0;" :: "n"(n) : "memory")

#define LDSM4(r0, r1, r2, r3, addr) \
    asm volatile("ldmatrix.sync.aligned.m8n8.x4.shared.b16 {%0,%1,%2,%3}, [%4];" \
        : "=r"(r0), "=r"(r1), "=r"(r2), "=r"(r3) : "r"(addr))

__device__ __forceinline__ void mma_f16(float* c, const uint32_t* a, const uint32_t* b) {
    asm volatile(
        "mma.sync.aligned.m16n8k16.row.col.f32.f16.f16.f32 "
        "{%0,%1,%2,%3}, {%4,%5,%6,%7}, {%8,%9}, {%0,%1,%2,%3};"
        : "+f"(c[0]), "+f"(c[1]), "+f"(c[2]), "+f"(c[3])
        : "r"(a[0]), "r"(a[1]), "r"(a[2]), "r"(a[3]), "r"(b[0]), "r"(b[1]));
}

__device__ __forceinline__ float sig_(float x) {
    x = fminf(fmaxf(x, -30.f), 30.f);
    return __fdividef(1.f, 1.f + __expf(-x));
}
__device__ __forceinline__ float tanh_(float x) {
    x = fminf(fmaxf(x, -15.f), 15.f);
    float e = __expf(2.f * x);
    return __fdividef(e - 1.f, e + 1.f);
}

// ---------------- merged precompute: A convert + W^T convert ----------------
__global__ __launch_bounds__(256) void prep_kernel(
    const float* __restrict__ hid, const float* __restrict__ inp,
    const float* __restrict__ Wf, const float* __restrict__ Wi,
    const float* __restrict__ Wc, const float* __restrict__ Wo)
{
    __shared__ float tile[32][33];
    const int bid = blockIdx.x;
    if (bid < 8192) {
        int i4 = bid * 256 + threadIdx.x;   // float4 index over [4096][512]
        int row = i4 >> 9;
        int c4  = i4 & 511;
        const float4 v = (c4 < 256)
            ? *(const float4*)&hid[(size_t)row * 1024 + c4 * 4]
            : *(const float4*)&inp[(size_t)row * 1024 + (c4 - 256) * 4];
        __half h[4];
        h[0] = __float2half_rn(v.x);
        h[1] = __float2half_rn(v.y);
        h[2] = __float2half_rn(v.z);
        h[3] = __float2half_rn(v.w);
        *(uint2*)&g_Ah[(size_t)row * KDIM + c4 * 4] = *(uint2*)h;
    } else {
        const int t  = bid - 8192;          // 8192 blocks: gate(4) x k(64) x n(32)
        const int g  = t >> 11;
        const int k0 = ((t >> 5) & 63) * 32;
        const int n0 = (t & 31) * 32;
        const float* W = (g == 0) ? Wf : (g == 1) ? Wi : (g == 2) ? Wc : Wo;
        const int tx = threadIdx.x & 31;
        const int ty = threadIdx.x >> 5;   // 0..7
        #pragma unroll
        for (int j = 0; j < 4; j++)
            tile[ty + 8 * j][tx] = W[(size_t)(k0 + ty + 8 * j) * UNITS + n0 + tx];
        __syncthreads();
        const int n_l = threadIdx.x >> 3;        // 0..31
        const int kq  = (threadIdx.x & 7) * 4;   // 0..28
        __half h[4];
        #pragma unroll
        for (int j = 0; j < 4; j++)
            h[j] = __float2half_rn(tile[kq + j][n_l]);
        size_t o = ((size_t)g * UNITS + n0 + n_l) * KDIM + k0 + kq;
        *(uint2*)&g_Bh[o] = *(uint2*)h;
    }
}

// ---------------- fused GEMM + register epilogue ----------------
__global__ __launch_bounds__(256, 2) void gemm_kernel(
    const float* __restrict__ cell,
    const float* __restrict__ bfp, const float* __restrict__ bip,
    const float* __restrict__ bcp, const float* __restrict__ bop,
    float* __restrict__ out_h, float* __restrict__ out_c)
{
    extern __shared__ char smem[];
    const uint32_t sb = smem_u32(smem);
    const int tid  = threadIdx.x;
    const int wid  = tid >> 5;
    const int lane = tid & 31;
    const int warp_m = wid & 1;    // 64 rows
    const int warp_n = wid >> 1;   // 0..3 -> 8 units each, all 4 gates
    const int m0 = blockIdx.y * BM;
    const int n0 = blockIdx.x * BNU;

    auto issue_stage = [&](int s) {
        const int k0 = s * BK;
        const uint32_t base = sb + (s & 1) * STAGE_B;
        #pragma unroll
        for (int i = 0; i < 4; i++) {
            const int idx = tid + i * 256;
            const int row = idx >> 3;
            const int c   = idx & 7;
            cp16(base + OFF_AH + row * ROW_B + c * 16,
                 &g_Ah[(size_t)(m0 + row) * KDIM + k0 + c * 8]);
            const size_t gr = (size_t)(row >> 5) * UNITS + n0 + (row & 31);
            cp16(base + OFF_BH + row * ROW_B + c * 16,
                 &g_Bh[gr * KDIM + k0 + c * 8]);
        }
        CP_COMMIT();
    };

    // ldmatrix lane addressing (byte offsets within tiles)
    const uint32_t a_off = (uint32_t)((warp_m * 64 + (lane & 15)) * ROW_B + (lane >> 4) * 16);
    // B: [gate 2p | gate 2p+1] x [k0-7 | k8-15] per LDSM4
    const uint32_t b_off = (uint32_t)((((lane >> 4) & 1) * 32 + warp_n * 8 + (lane & 7)) * ROW_B
                                      + ((lane >> 3) & 1) * 16);

    float acc[4][4][4];   // [mt rows][gate][q]
    #pragma unroll
    for (int i = 0; i < 4; i++)
        #pragma unroll
        for (int j = 0; j < 4; j++)
            #pragma unroll
            for (int q = 0; q < 4; q++) acc[i][j][q] = 0.f;

    issue_stage(0);

    // Single-barrier pipeline: the barrier that publishes stage s also
    // certifies everyone finished reading stage s-1, so issue(s+1) can
    // safely overwrite buffer (s+1)&1 right after it.
    #pragma unroll 1
    for (int s = 0; s < NSTAGE; s++) {
        CP_WAIT(0);
        __syncthreads();
        if (s + 1 < NSTAGE) issue_stage(s + 1);

        const uint32_t base = sb + (s & 1) * STAGE_B;
        #pragma unroll
        for (int ksub = 0; ksub < 4; ksub++) {
            const uint32_t kb = ksub * 32;
            uint32_t aH[4][4], bH[4][2];
            #pragma unroll
            for (int mt = 0; mt < 4; mt++) {
                const uint32_t ra = base + a_off + mt * 16 * ROW_B + kb;
                LDSM4(aH[mt][0], aH[mt][1], aH[mt][2], aH[mt][3], ra + OFF_AH);
            }
            #pragma unroll
            for (int p = 0; p < 2; p++) {
                const uint32_t rb = base + b_off + p * 64 * ROW_B + kb;
                LDSM4(bH[2*p][0], bH[2*p][1], bH[2*p+1][0], bH[2*p+1][1], rb + OFF_BH);
            }
            #pragma unroll
            for (int mt = 0; mt < 4; mt++)
                #pragma unroll
                for (int g = 0; g < 4; g++)
                    mma_f16(acc[mt][g], aH[mt], bH[g]);
        }
    }

    // ---- register-direct epilogue
    const int fr = lane >> 2;
    const int fc = (lane & 3) * 2;
    const int ucol = n0 + warp_n * 8 + fc;
    const float2 Bf = *(const float2*)&bfp[ucol];
    const float2 Bi = *(const float2*)&bip[ucol];
    const float2 Bc = *(const float2*)&bcp[ucol];
    const float2 Bo = *(const float2*)&bop[ucol];

    #pragma unroll
    for (int mt = 0; mt < 4; mt++) {
        #pragma unroll
        for (int q = 0; q < 2; q++) {
            const int row = m0 + warp_m * 64 + mt * 16 + fr + q * 8;
            const size_t go = (size_t)row * UNITS + ucol;
            const float2 cp = *(const float2*)&cell[go];
            const float pf0 = acc[mt][0][2*q],   pf1 = acc[mt][0][2*q+1];
            const float pi0 = acc[mt][1][2*q],   pi1 = acc[mt][1][2*q+1];
            const float pc0 = acc[mt][2][2*q],   pc1 = acc[mt][2][2*q+1];
            const float po0 = acc[mt][3][2*q],   po1 = acc[mt][3][2*q+1];

            float2 nh, nc;
            {
                const float f  = sig_(pf0 + Bf.x), ig = sig_(pi0 + Bi.x);
                const float cc = tanh_(pc0 + Bc.x), o = sig_(po0 + Bo.x);
                nc.x = f * cp.x + ig * cc; nh.x = o * tanh_(nc.x);
            }
            {
                const float f  = sig_(pf1 + Bf.y), ig = sig_(pi1 + Bi.y);
                const float cc = tanh_(pc1 + Bc.y), o = sig_(po1 + Bo.y);
                nc.y = f * cp.y + ig * cc; nh.y = o * tanh_(nc.y);
            }
            *(float2*)&out_h[go] = nh;
            *(float2*)&out_c[go] = nc;
        }
    }
}

// ---------------- host launch ----------------
extern "C" void kernel_launch(void* const* d_in, const int* in_sizes, int n_in,
                              void* d_out, int out_size) {
    const float* inp  = (const float*)d_in[0];
    const float* hid  = (const float*)d_in[1];
    const float* cell = (const float*)d_in[2];
    const float* Wf   = (const float*)d_in[3];
    const float* bf   = (const float*)d_in[4];
    const float* Wi   = (const float*)d_in[5];
    const float* bi   = (const float*)d_in[6];
    const float* Wc   = (const float*)d_in[7];
    const float* bc   = (const float*)d_in[8];
    const float* Wo   = (const float*)d_in[9];
    const float* bo   = (const float*)d_in[10];

    float* out_h = (float*)d_out;
    float* out_c = out_h + (size_t)BATCH * UNITS;

    cudaFuncSetAttribute(gemm_kernel,
                         cudaFuncAttributeMaxDynamicSharedMemorySize, SMEM_TOTAL);

    prep_kernel<<<16384, 256>>>(hid, inp, Wf, Wi, Wc, Wo);
    gemm_kernel<<<dim3(UNITS / BNU, BATCH / BM), 256, SMEM_TOTAL>>>(
        cell, bf, bi, bc, bo, out_h, out_c);
}

// round 12
// speedup vs baseline: 1.9663x; 1.0101x over previous
#include <cuda_runtime.h>
#include <cuda_fp16.h>
#include <cstdint>
#include <math.h>

// LSTM cell: fp16 mma.sync GEMM + register-direct fused gate epilogue.
// Round 12: 3-buffer cp.async pipeline with 2 stages in flight (CP_WAIT(1)),
// single barrier per stage; vectorized A-prep.

#define BATCH 4096
#define UNITS 1024
#define KDIM  2048

#define BM 128
#define BNU 32              // units per CTA (x4 gates = 128 gemm cols)
#define BK 64
#define NSTAGE (KDIM / BK)  // 32
#define NBUF 3

#define ROW_B   144                     // 128B data + 16B pad (conflict-free)
#define TILE_B  (128 * ROW_B)           // 18432
#define OFF_AH  0
#define OFF_BH  TILE_B
#define STAGE_B (2 * TILE_B)            // 36864
#define SMEM_TOTAL (NBUF * STAGE_B)     // 110592 (x2 CTAs = 221KB <= 228KB)

// ---------------- device scratch ----------------
__device__ __half g_Ah[(size_t)BATCH * KDIM];
__device__ __half g_Bh[(size_t)4 * UNITS * KDIM];   // row = gate*1024 + n, k contiguous

// ---------------- helpers ----------------
__device__ __forceinline__ uint32_t smem_u32(const void* p) {
    uint32_t a;
    asm("{ .reg .u64 t; cvta.to.shared.u64 t, %1; cvt.u32.u64 %0, t; }" : "=r"(a) : "l"(p));
    return a;
}
__device__ __forceinline__ void cp16(uint32_t dst, const void* src) {
    asm volatile("cp.async.cg.shared.global [%0], [%1], 16;" :: "r"(dst), "l"(src));
}
#define CP_COMMIT() asm volatile("cp.async.commit_group;" ::: "memory")
#define CP_WAIT(n)  asm volatile("cp.async.wait_group %0;" :: "n"(n) : "memory")

#define LDSM4(r0, r1, r2, r3, addr) \
    asm volatile("ldmatrix.sync.aligned.m8n8.x4.shared.b16 {%0,%1,%2,%3}, [%4];" \
        : "=r"(r0), "=r"(r1), "=r"(r2), "=r"(r3) : "r"(addr))

__device__ __forceinline__ void mma_f16(float* c, const uint32_t* a, const uint32_t* b) {
    asm volatile(
        "mma.sync.aligned.m16n8k16.row.col.f32.f16.f16.f32 "
        "{%0,%1,%2,%3}, {%4,%5,%6,%7}, {%8,%9}, {%0,%1,%2,%3};"
        : "+f"(c[0]), "+f"(c[1]), "+f"(c[2]), "+f"(c[3])
        : "r"(a[0]), "r"(a[1]), "r"(a[2]), "r"(a[3]), "r"(b[0]), "r"(b[1]));
}

__device__ __forceinline__ float sig_(float x) {
    x = fminf(fmaxf(x, -30.f), 30.f);
    return __fdividef(1.f, 1.f + __expf(-x));
}
__device__ __forceinline__ float tanh_(float x) {
    x = fminf(fmaxf(x, -15.f), 15.f);
    float e = __expf(2.f * x);
    return __fdividef(e - 1.f, e + 1.f);
}

// ---------------- merged precompute: A convert + W^T convert ----------------
// blocks [0, 4096): A convert (1 row each, 8 floats/thread, uint4 store)
// blocks [4096, 12288): B transpose+convert
__global__ __launch_bounds__(256) void prep_kernel(
    const float* __restrict__ hid, const float* __restrict__ inp,
    const float* __restrict__ Wf, const float* __restrict__ Wi,
    const float* __restrict__ Wc, const float* __restrict__ Wo)
{
    __shared__ float tile[32][33];
    const int bid = blockIdx.x;
    if (bid < 4096) {
        const int row = bid;
        const int c8  = threadIdx.x * 8;   // 0..2040
        const float* src = (c8 < 1024) ? &hid[(size_t)row * 1024 + c8]
                                       : &inp[(size_t)row * 1024 + (c8 - 1024)];
        const float4 v0 = *(const float4*)src;
        const float4 v1 = *(const float4*)(src + 4);
        __half h[8];
        h[0] = __float2half_rn(v0.x); h[1] = __float2half_rn(v0.y);
        h[2] = __float2half_rn(v0.z); h[3] = __float2half_rn(v0.w);
        h[4] = __float2half_rn(v1.x); h[5] = __float2half_rn(v1.y);
        h[6] = __float2half_rn(v1.z); h[7] = __float2half_rn(v1.w);
        *(uint4*)&g_Ah[(size_t)row * KDIM + c8] = *(uint4*)h;
    } else {
        const int t  = bid - 4096;          // 8192 blocks: gate(4) x k(64) x n(32)
        const int g  = t >> 11;
        const int k0 = ((t >> 5) & 63) * 32;
        const int n0 = (t & 31) * 32;
        const float* W = (g == 0) ? Wf : (g == 1) ? Wi : (g == 2) ? Wc : Wo;
        const int tx = threadIdx.x & 31;
        const int ty = threadIdx.x >> 5;   // 0..7
        #pragma unroll
        for (int j = 0; j < 4; j++)
            tile[ty + 8 * j][tx] = W[(size_t)(k0 + ty + 8 * j) * UNITS + n0 + tx];
        __syncthreads();
        const int n_l = threadIdx.x >> 3;        // 0..31
        const int kq  = (threadIdx.x & 7) * 4;   // 0..28
        __half h[4];
        #pragma unroll
        for (int j = 0; j < 4; j++)
            h[j] = __float2half_rn(tile[kq + j][n_l]);
        size_t o = ((size_t)g * UNITS + n0 + n_l) * KDIM + k0 + kq;
        *(uint2*)&g_Bh[o] = *(uint2*)h;
    }
}

// ---------------- fused GEMM + register epilogue ----------------
__global__ __launch_bounds__(256, 2) void gemm_kernel(
    const float* __restrict__ cell,
    const float* __restrict__ bfp, const float* __restrict__ bip,
    const float* __restrict__ bcp, const float* __restrict__ bop,
    float* __restrict__ out_h, float* __restrict__ out_c)
{
    extern __shared__ char smem[];
    const uint32_t sb = smem_u32(smem);
    const int tid  = threadIdx.x;
    const int wid  = tid >> 5;
    const int lane = tid & 31;
    const int warp_m = wid & 1;    // 64 rows
    const int warp_n = wid >> 1;   // 0..3 -> 8 units each, all 4 gates
    const int m0 = blockIdx.y * BM;
    const int n0 = blockIdx.x * BNU;

    auto issue_stage = [&](int s) {
        const int k0 = s * BK;
        const uint32_t base = sb + (s % NBUF) * STAGE_B;
        #pragma unroll
        for (int i = 0; i < 4; i++) {
            const int idx = tid + i * 256;
            const int row = idx >> 3;
            const int c   = idx & 7;
            cp16(base + OFF_AH + row * ROW_B + c * 16,
                 &g_Ah[(size_t)(m0 + row) * KDIM + k0 + c * 8]);
            const size_t gr = (size_t)(row >> 5) * UNITS + n0 + (row & 31);
            cp16(base + OFF_BH + row * ROW_B + c * 16,
                 &g_Bh[gr * KDIM + k0 + c * 8]);
        }
        CP_COMMIT();
    };

    // ldmatrix lane addressing (byte offsets within tiles)
    const uint32_t a_off = (uint32_t)((warp_m * 64 + (lane & 15)) * ROW_B + (lane >> 4) * 16);
    // B: [gate 2p | gate 2p+1] x [k0-7 | k8-15] per LDSM4
    const uint32_t b_off = (uint32_t)((((lane >> 4) & 1) * 32 + warp_n * 8 + (lane & 7)) * ROW_B
                                      + ((lane >> 3) & 1) * 16);

    float acc[4][4][4];   // [mt rows][gate][q]
    #pragma unroll
    for (int i = 0; i < 4; i++)
        #pragma unroll
        for (int j = 0; j < 4; j++)
            #pragma unroll
            for (int q = 0; q < 4; q++) acc[i][j][q] = 0.f;

    issue_stage(0);
    issue_stage(1);

    // Single barrier per stage; two cp.async groups in flight.
    // Barrier at stage s certifies compute(s-1) done by all warps, so
    // issue(s+2) may overwrite buffer (s+2)%3 == (s-1)%3 right after it.
    #pragma unroll 1
    for (int s = 0; s < NSTAGE; s++) {
        if (s + 1 < NSTAGE) { CP_WAIT(1); } else { CP_WAIT(0); }
        __syncthreads();
        if (s + 2 < NSTAGE) issue_stage(s + 2);

        const uint32_t base = sb + (s % NBUF) * STAGE_B;
        #pragma unroll
        for (int ksub = 0; ksub < 4; ksub++) {
            const uint32_t kb = ksub * 32;
            uint32_t aH[4][4], bH[4][2];
            #pragma unroll
            for (int mt = 0; mt < 4; mt++) {
                const uint32_t ra = base + a_off + mt * 16 * ROW_B + kb;
                LDSM4(aH[mt][0], aH[mt][1], aH[mt][2], aH[mt][3], ra + OFF_AH);
            }
            #pragma unroll
            for (int p = 0; p < 2; p++) {
                const uint32_t rb = base + b_off + p * 64 * ROW_B + kb;
                LDSM4(bH[2*p][0], bH[2*p][1], bH[2*p+1][0], bH[2*p+1][1], rb + OFF_BH);
            }
            #pragma unroll
            for (int mt = 0; mt < 4; mt++)
                #pragma unroll
                for (int g = 0; g < 4; g++)
                    mma_f16(acc[mt][g], aH[mt], bH[g]);
        }
    }

    // ---- register-direct epilogue
    const int fr = lane >> 2;
    const int fc = (lane & 3) * 2;
    const int ucol = n0 + warp_n * 8 + fc;
    const float2 Bf = *(const float2*)&bfp[ucol];
    const float2 Bi = *(const float2*)&bip[ucol];
    const float2 Bc = *(const float2*)&bcp[ucol];
    const float2 Bo = *(const float2*)&bop[ucol];

    #pragma unroll
    for (int mt = 0; mt < 4; mt++) {
        #pragma unroll
        for (int q = 0; q < 2; q++) {
            const int row = m0 + warp_m * 64 + mt * 16 + fr + q * 8;
            const size_t go = (size_t)row * UNITS + ucol;
            const float2 cp = *(const float2*)&cell[go];
            const float pf0 = acc[mt][0][2*q],   pf1 = acc[mt][0][2*q+1];
            const float pi0 = acc[mt][1][2*q],   pi1 = acc[mt][1][2*q+1];
            const float pc0 = acc[mt][2][2*q],   pc1 = acc[mt][2][2*q+1];
            const float po0 = acc[mt][3][2*q],   po1 = acc[mt][3][2*q+1];

            float2 nh, nc;
            {
                const float f  = sig_(pf0 + Bf.x), ig = sig_(pi0 + Bi.x);
                const float cc = tanh_(pc0 + Bc.x), o = sig_(po0 + Bo.x);
                nc.x = f * cp.x + ig * cc; nh.x = o * tanh_(nc.x);
            }
            {
                const float f  = sig_(pf1 + Bf.y), ig = sig_(pi1 + Bi.y);
                const float cc = tanh_(pc1 + Bc.y), o = sig_(po1 + Bo.y);
                nc.y = f * cp.y + ig * cc; nh.y = o * tanh_(nc.y);
            }
            *(float2*)&out_h[go] = nh;
            *(float2*)&out_c[go] = nc;
        }
    }
}

// ---------------- host launch ----------------
extern "C" void kernel_launch(void* const* d_in, const int* in_sizes, int n_in,
                              void* d_out, int out_size) {
    const float* inp  = (const float*)d_in[0];
    const float* hid  = (const float*)d_in[1];
    const float* cell = (const float*)d_in[2];
    const float* Wf   = (const float*)d_in[3];
    const float* bf   = (const float*)d_in[4];
    const float* Wi   = (const float*)d_in[5];
    const float* bi   = (const float*)d_in[6];
    const float* Wc   = (const float*)d_in[7];
    const float* bc   = (const float*)d_in[8];
    const float* Wo   = (const float*)d_in[9];
    const float* bo   = (const float*)d_in[10];

    float* out_h = (float*)d_out;
    float* out_c = out_h + (size_t)BATCH * UNITS;

    cudaFuncSetAttribute(gemm_kernel,
                         cudaFuncAttributeMaxDynamicSharedMemorySize, SMEM_TOTAL);

    prep_kernel<<<12288, 256>>>(hid, inp, Wf, Wi, Wc, Wo);
    gemm_kernel<<<dim3(UNITS / BNU, BATCH / BM), 256, SMEM_TOTAL>>>(
        cell, bf, bi, bc, bo, out_h, out_c);
}